// round 12
// baseline (speedup 1.0000x reference)
#include <cuda_runtime.h>
#include <mma.h>
#include <math.h>
#include <stdint.h>

using namespace nvcuda;

#define HH 16
#define TT 2048
#define DQK 192
#define NOPEC 128
#define ROPEC 64
#define LORAC 512
#define VDIMC 128
#define SCALE_F 0.07216878364870323f   // 1/sqrt(192)

// Device scratch (no allocation allowed)
__device__ float g_KnT[HH * NOPEC * TT];  // per-head k_nope TRANSPOSED [d][t], tf32-rounded
__device__ float g_V  [HH * TT * VDIMC];  // absorbed V_h [t][v], tf32-rounded
__device__ float g_ropeT[ROPEC * TT];     // k_pe TRANSPOSED [d][t], tf32-rounded

__device__ __forceinline__ float tf32r(float x) {
    uint32_t u;
    asm("cvt.rna.tf32.f32 %0, %1;" : "=r"(u) : "f"(x));
    return __uint_as_float(u);
}
__device__ __forceinline__ float4 tf32r4(float4 v) {
    return make_float4(tf32r(v.x), tf32r(v.y), tf32r(v.z), tf32r(v.w));
}
__device__ __forceinline__ uint32_t smem_u32(const void* p) {
    uint32_t a;
    asm("{ .reg .u64 t; cvta.to.shared.u64 t, %1; cvt.u32.u64 %0, t; }" : "=r"(a) : "l"(p));
    return a;
}
#define CP_ASYNC16(saddr, gptr) \
    asm volatile("cp.async.cg.shared.global [%0], [%1], 16;" :: "r"(saddr), "l"(gptr))
#define CP_COMMIT() asm volatile("cp.async.commit_group;" ::: "memory")
#define CP_WAIT(n)  asm volatile("cp.async.wait_group %0;" :: "n"(n) : "memory")

typedef wmma::fragment<wmma::matrix_a, 16, 16, 8, wmma::precision::tf32, wmma::row_major> FragA;
typedef wmma::fragment<wmma::matrix_b, 16, 16, 8, wmma::precision::tf32, wmma::row_major> FragBr;
typedef wmma::fragment<wmma::accumulator, 16, 16, 8, float> FragC;

// ---------------------------------------------------------------------------
// Kernel 1: prep GEMM (BK=32, 128-reg body). Part 0 -> g_KnT via smem-staged
// transpose (ST_LD multiple of 4 — wmma ldm requirement); part 1 -> g_V.
// ---------------------------------------------------------------------------
#define AS_LD 36
#define BS_LD 132
#define ST_LD 132                                // MUST be multiple of 4 for f32 wmma ldm

__global__ __launch_bounds__(256) void kv_gemm_wmma(
    const float* __restrict__ kc, const float* __restrict__ wkv, const float* __restrict__ wuv)
{
    const int m0 = blockIdx.x * 128, part = blockIdx.y, h = blockIdx.z;
    __shared__ float smbuf[8832];                // As[128*36] | Bs[32*132]; reused: staging 64*132=8448
    float* As = smbuf;
    float* Bs = smbuf + 128 * AS_LD;

    const int tid = threadIdx.x, wid = tid >> 5;
    const int wr = wid & 3, wc = wid >> 2;

    const float* Bsrc; int bstride;
    if (part == 0) { Bsrc = wkv + h * 256;             bstride = HH * 256; }
    else           { Bsrc = wuv + h * (LORAC * VDIMC); bstride = VDIMC;    }

    FragC acc[2][4];
    #pragma unroll
    for (int i = 0; i < 2; i++)
        #pragma unroll
        for (int j = 0; j < 4; j++) wmma::fill_fragment(acc[i][j], 0.f);

    for (int k0 = 0; k0 < LORAC; k0 += 32) {
        #pragma unroll
        for (int it = 0; it < 4; it++) {
            int i = tid + it * 256;
            int r = i >> 3, c4 = (i & 7) << 2;
            float4 v = tf32r4(*(const float4*)(kc + (size_t)(m0 + r) * LORAC + k0 + c4));
            *(float4*)&As[r * AS_LD + c4] = v;
        }
        #pragma unroll
        for (int it = 0; it < 4; it++) {
            int i = tid + it * 256;
            int k = i >> 5, n4 = (i & 31) << 2;
            float4 v = tf32r4(*(const float4*)(Bsrc + (size_t)(k0 + k) * bstride + n4));
            *(float4*)&Bs[k * BS_LD + n4] = v;
        }
        __syncthreads();

        #pragma unroll
        for (int ks = 0; ks < 4; ks++) {
            FragA a[2];
            FragBr b[4];
            #pragma unroll
            for (int i = 0; i < 2; i++)
                wmma::load_matrix_sync(a[i], As + (wr * 32 + 16 * i) * AS_LD + ks * 8, AS_LD);
            #pragma unroll
            for (int j = 0; j < 4; j++)
                wmma::load_matrix_sync(b[j], Bs + (ks * 8) * BS_LD + wc * 64 + 16 * j, BS_LD);
            #pragma unroll
            for (int i = 0; i < 2; i++)
                #pragma unroll
                for (int j = 0; j < 4; j++)
                    wmma::mma_sync(acc[i][j], a[i], b[j], acc[i][j]);
        }
        __syncthreads();
    }

    #pragma unroll
    for (int i = 0; i < 2; i++)
        #pragma unroll
        for (int j = 0; j < 4; j++)
            #pragma unroll
            for (int e = 0; e < acc[i][j].num_elements; e++)
                acc[i][j].x[e] = tf32r(acc[i][j].x[e]);

    if (part == 1) {
        #pragma unroll
        for (int i = 0; i < 2; i++)
            #pragma unroll
            for (int j = 0; j < 4; j++) {
                float* p = g_V + (size_t)h * TT * VDIMC
                         + (size_t)(m0 + wr * 32 + 16 * i) * VDIMC + wc * 64 + 16 * j;
                wmma::store_matrix_sync(p, acc[i][j], VDIMC, wmma::mem_row_major);
            }
    } else {
        // staged transpose: two passes of 64 m-rows; coalesced g_KnT writes
        #pragma unroll
        for (int p = 0; p < 2; p++) {
            __syncthreads();
            if ((wr >> 1) == p) {
                #pragma unroll
                for (int i = 0; i < 2; i++)
                    #pragma unroll
                    for (int j = 0; j < 4; j++)
                        wmma::store_matrix_sync(
                            smbuf + ((wr & 1) * 32 + 16 * i) * ST_LD + wc * 64 + 16 * j,
                            acc[i][j], ST_LD, wmma::mem_row_major);
            }
            __syncthreads();
            #pragma unroll
            for (int it = 0; it < 8; it++) {
                int i = tid + it * 256;          // 2048 float4 over 128(d) x 64(t)
                int d = i >> 4, t4 = (i & 15) << 2;
                float4 v = make_float4(smbuf[(t4 + 0) * ST_LD + d],
                                       smbuf[(t4 + 1) * ST_LD + d],
                                       smbuf[(t4 + 2) * ST_LD + d],
                                       smbuf[(t4 + 3) * ST_LD + d]);
                *(float4*)(g_KnT + (size_t)h * NOPEC * TT + (size_t)d * TT + m0 + 64 * p + t4) = v;
            }
        }
    }
}

// Kernel 1b: rope transpose + tf32 round (tiny)
__global__ void rope_t_kernel(const float* __restrict__ kpe)
{
    int i = blockIdx.x * blockDim.x + threadIdx.x;
    if (i >= TT * ROPEC) return;
    int t = i >> 6, d = i & 63;
    g_ropeT[(size_t)d * TT + t] = tf32r(kpe[i]);
}

// ---------------------------------------------------------------------------
// Kernel 2: wmma-tf32 causal flash attention. 512 threads, 16 warps (4x4).
//   Warp tiles: S 16x16, O 16x32. Q cols 0..95 in regs (aq[12]),
//   cols 96..191 in persistent smem. Transposed K, register exp,
//   ones-MMA rowsum, cp.async double buffer.
// ---------------------------------------------------------------------------
#define NTHR 512
#define KT_LD 72
#define VS_LD 132
#define PS_LD 68
#define QT_LD 100
#define LB_LD 20                                 // multiple of 4 (f32 wmma ldm req)
#define KT_BYTES (192 * KT_LD * 4)               // 55296
#define VBYTES   (64 * VS_LD * 4)                // 33792
#define SM_K0 0
#define SM_K1 KT_BYTES
#define SM_V0 (2 * KT_BYTES)                     // 110592
#define SM_V1 (2 * KT_BYTES + VBYTES)            // 144384
#define SM_PS (2 * KT_BYTES + 2 * VBYTES)        // 178176
#define SM_QT (SM_PS + 64 * PS_LD * 4)           // 195584
#define SM_LB (SM_QT + 64 * QT_LD * 4)           // 221184
#define FLASH_SMEM (SM_LB + 64 * LB_LD * 4)      // 226304

__device__ __forceinline__ void prefetch_tile(
    uint32_t sb, int buf, int jt, int tid,
    const float* __restrict__ KnTh, const float* __restrict__ Vh)
{
    const uint32_t kb = sb + (buf ? SM_K1 : SM_K0);
    const uint32_t vb = sb + (buf ? SM_V1 : SM_V0);
    #pragma unroll
    for (int it = 0; it < 4; it++) {
        int i = tid + it * NTHR;                 // 2048 float4 (K^T nope rows 0..127)
        int r = i >> 4, c4 = (i & 15) << 2;
        CP_ASYNC16(kb + (uint32_t)(r * KT_LD + c4) * 4,
                   KnTh + (size_t)r * TT + jt * 64 + c4);
    }
    #pragma unroll
    for (int it = 0; it < 2; it++) {
        int i = tid + it * NTHR;                 // 1024 float4 (rope rows 128..191)
        int r = i >> 4, c4 = (i & 15) << 2;
        CP_ASYNC16(kb + (uint32_t)((128 + r) * KT_LD + c4) * 4,
                   g_ropeT + (size_t)r * TT + jt * 64 + c4);
    }
    #pragma unroll
    for (int it = 0; it < 4; it++) {
        int i = tid + it * NTHR;                 // 2048 float4 (V 64x128)
        int r = i >> 5, c4 = (i & 31) << 2;
        CP_ASYNC16(vb + (uint32_t)(r * VS_LD + c4) * 4,
                   Vh + (size_t)(jt * 64 + r) * VDIMC + c4);
    }
    CP_COMMIT();
}

__global__ __launch_bounds__(NTHR) void flash_wmma(
    const float* __restrict__ q, float* __restrict__ out)
{
    const int bid = blockIdx.x;
    const int h = bid & 15, idx = bid >> 4;
    const int qt = (idx & 1) ? (idx >> 1) : (31 - (idx >> 1));  // heavy/light interleave

    extern __shared__ char smem[];
    const uint32_t sb = smem_u32(smem);
    float* Ps = (float*)(smem + SM_PS);
    float* Qt = (float*)(smem + SM_QT);
    float* Lb = (float*)(smem + SM_LB);

    const int tid = threadIdx.x, wid = tid >> 5;
    const int wr = wid & 3, wc = wid >> 2;   // 4x4 warp grid: row (x16), col (x16)

    // ---- stage Q 64x192 into K0 region (LD 200) ----
    {
        float* Qstage = (float*)(smem + SM_K0);
        #pragma unroll
        for (int it = 0; it < 6; it++) {
            int i = tid + it * NTHR;             // 3072 float4
            int r = i / 48, c4 = (i % 48) * 4;
            float4 v = tf32r4(*(const float4*)(q + ((size_t)(qt * 64 + r) * HH + h) * DQK + c4));
            *(float4*)&Qstage[r * 200 + c4] = v;
        }
    }
    __syncthreads();

    // per-warp A-frags for Q cols 0..95; copy cols 96..191 to persistent Qt
    FragA aq[12];
    {
        float* Qstage = (float*)(smem + SM_K0);
        #pragma unroll
        for (int ks = 0; ks < 12; ks++)
            wmma::load_matrix_sync(aq[ks], Qstage + (wr * 16) * 200 + ks * 8, 200);
        #pragma unroll
        for (int it = 0; it < 3; it++) {
            int i = tid + it * NTHR;             // 1536 float4 (64 x 96)
            int r = i / 24, c4 = (i % 24) * 4;
            *(float4*)&Qt[r * QT_LD + c4] = *(float4*)&Qstage[r * 200 + 96 + c4];
        }
    }
    __syncthreads();

    FragC oacc[2], osum;
    wmma::fill_fragment(oacc[0], 0.f);
    wmma::fill_fragment(oacc[1], 0.f);
    wmma::fill_fragment(osum, 0.f);
    FragBr onesb;
    wmma::fill_fragment(onesb, 1.0f);

    const float* KnTh = g_KnT + (size_t)h * NOPEC * TT;
    const float* Vh   = g_V   + (size_t)h * TT * VDIMC;

    prefetch_tile(sb, 0, 0, tid, KnTh, Vh);

    for (int jt = 0; jt <= qt; jt++) {
        if (jt < qt) {
            prefetch_tile(sb, (jt + 1) & 1, jt + 1, tid, KnTh, Vh);
            CP_WAIT(1);
        } else {
            CP_WAIT(0);
        }
        __syncthreads();

        float* Kt = (float*)(smem + ((jt & 1) ? SM_K1 : SM_K0));
        float* Vs = (float*)(smem + ((jt & 1) ? SM_V1 : SM_V0));

        // ---- S = Q @ K^T (warp 16x16; B rows contiguous) ----
        {
            FragC sacc;
            wmma::fill_fragment(sacc, 0.f);
            #pragma unroll
            for (int ks = 0; ks < 24; ks++) {
                FragA a;
                if (ks < 12) a = aq[ks];
                else wmma::load_matrix_sync(a, Qt + (wr * 16) * QT_LD + (ks * 8 - 96), QT_LD);
                FragBr b;
                wmma::load_matrix_sync(b, Kt + (ks * 8) * KT_LD + wc * 16, KT_LD);
                wmma::mma_sync(sacc, a, b, sacc);
            }
            #pragma unroll
            for (int e = 0; e < sacc.num_elements; e++)
                sacc.x[e] = tf32r(__expf(sacc.x[e] * SCALE_F));
            wmma::store_matrix_sync(Ps + (wr * 16) * PS_LD + wc * 16, sacc, PS_LD, wmma::mem_row_major);
        }
        __syncthreads();

        // ---- diagonal tile: zero masked entries in smem ----
        if (jt == qt) {
            const int srow = tid >> 3, scg = tid & 7;
            float* prow = Ps + srow * PS_LD + scg * 8;
            #pragma unroll
            for (int c = 0; c < 8; c++)
                if (scg * 8 + c > srow) prow[c] = 0.f;
            __syncthreads();
        }

        // ---- O += P @ V (warp 16x32); osum += P @ ones (wc==0) ----
        #pragma unroll
        for (int ks = 0; ks < 8; ks++) {
            FragA a;
            wmma::load_matrix_sync(a, Ps + (wr * 16) * PS_LD + ks * 8, PS_LD);
            #pragma unroll
            for (int j = 0; j < 2; j++) {
                FragBr b;
                wmma::load_matrix_sync(b, Vs + (ks * 8) * VS_LD + wc * 32 + 16 * j, VS_LD);
                wmma::mma_sync(oacc[j], a, b, oacc[j]);
            }
            if (wc == 0) wmma::mma_sync(osum, a, onesb, osum);
        }
        __syncthreads();
    }

    // ---- row sums (all 16 cols of osum identical; read col 0) ----
    if (wc == 0)
        wmma::store_matrix_sync(Lb + wr * 16 * LB_LD, osum, LB_LD, wmma::mem_row_major);
    // ---- stage O (V0 buffer), normalize, store ----
    float* Os = (float*)(smem + SM_V0);
    #pragma unroll
    for (int j = 0; j < 2; j++)
        wmma::store_matrix_sync(Os + (wr * 16) * VS_LD + wc * 32 + 16 * j,
                                oacc[j], VS_LD, wmma::mem_row_major);
    __syncthreads();

    #pragma unroll
    for (int it = 0; it < 4; it++) {
        int i = tid + it * NTHR;                 // 2048 float4
        int r = i >> 5, c4 = (i & 31) << 2;
        float inv = 1.f / Lb[r * LB_LD];
        float4 v = *(float4*)&Os[r * VS_LD + c4];
        *(float4*)(out + (size_t)(qt * 64 + r) * (HH * VDIMC) + h * VDIMC + c4) =
            make_float4(v.x * inv, v.y * inv, v.z * inv, v.w * inv);
    }
}

// ---------------------------------------------------------------------------
extern "C" void kernel_launch(void* const* d_in, const int* in_sizes, int n_in,
                              void* d_out, int out_size)
{
    (void)in_sizes; (void)n_in; (void)out_size;
    const float* q   = (const float*)d_in[0];   // (T, H, 192)
    const float* kc  = (const float*)d_in[1];   // (T, 512)
    const float* kpe = (const float*)d_in[2];   // (T, 64)
    const float* wkv = (const float*)d_in[3];   // (512, 4096)
    const float* wuv = (const float*)d_in[4];   // (16, 512, 128)
    float* out = (float*)d_out;                 // (T, 2048)

    cudaFuncSetAttribute(flash_wmma, cudaFuncAttributeMaxDynamicSharedMemorySize, FLASH_SMEM);

    dim3 g1(TT / 128, 2, HH);
    kv_gemm_wmma<<<g1, 256>>>(kc, wkv, wuv);
    rope_t_kernel<<<(TT * ROPEC + 255) / 256, 256>>>(kpe);

    flash_wmma<<<(TT / 64) * HH, NTHR, FLASH_SMEM>>>(q, out);
}

// round 13
// speedup vs baseline: 1.0530x; 1.0530x over previous
#include <cuda_runtime.h>
#include <mma.h>
#include <math.h>
#include <stdint.h>

using namespace nvcuda;

#define HH 16
#define TT 2048
#define DQK 192
#define NOPEC 128
#define ROPEC 64
#define LORAC 512
#define VDIMC 128
#define SCALE_F 0.07216878364870323f   // 1/sqrt(192)

// Device scratch (no allocation allowed)
__device__ float g_Kn[HH * TT * NOPEC];   // per-head k_nope [t][d], tf32-rounded
__device__ float g_V [HH * TT * VDIMC];   // absorbed V_h [t][v], tf32-rounded
__device__ float g_rope[TT * ROPEC];      // k_pe [t][d], tf32-rounded

__device__ __forceinline__ float tf32r(float x) {
    uint32_t u;
    asm("cvt.rna.tf32.f32 %0, %1;" : "=r"(u) : "f"(x));
    return __uint_as_float(u);
}
__device__ __forceinline__ float4 tf32r4(float4 v) {
    return make_float4(tf32r(v.x), tf32r(v.y), tf32r(v.z), tf32r(v.w));
}
__device__ __forceinline__ uint32_t smem_u32(const void* p) {
    uint32_t a;
    asm("{ .reg .u64 t; cvta.to.shared.u64 t, %1; cvt.u32.u64 %0, t; }" : "=r"(a) : "l"(p));
    return a;
}
#define CP_ASYNC16(saddr, gptr) \
    asm volatile("cp.async.cg.shared.global [%0], [%1], 16;" :: "r"(saddr), "l"(gptr))
#define CP_COMMIT() asm volatile("cp.async.commit_group;" ::: "memory")
#define CP_WAIT(n)  asm volatile("cp.async.wait_group %0;" :: "n"(n) : "memory")

typedef wmma::fragment<wmma::matrix_a, 16, 16, 8, wmma::precision::tf32, wmma::row_major> FragA;
typedef wmma::fragment<wmma::matrix_b, 16, 16, 8, wmma::precision::tf32, wmma::row_major> FragBr;
typedef wmma::fragment<wmma::matrix_b, 16, 16, 8, wmma::precision::tf32, wmma::col_major> FragBc;
typedef wmma::fragment<wmma::accumulator, 16, 16, 8, float> FragC;

// ---------------------------------------------------------------------------
// Kernel 1: tensorized prep GEMM, BK=32, row-major stores (R8/R9 version,
// 144us, 128 regs).
// ---------------------------------------------------------------------------
#define AS_LD 36
#define BS_LD 132

__global__ __launch_bounds__(256) void kv_gemm_wmma(
    const float* __restrict__ kc, const float* __restrict__ wkv, const float* __restrict__ wuv)
{
    const int m0 = blockIdx.x * 128, part = blockIdx.y, h = blockIdx.z;
    __shared__ float As[128 * AS_LD];
    __shared__ float Bs[32 * BS_LD];

    const int tid = threadIdx.x, wid = tid >> 5;
    const int wr = wid & 3, wc = wid >> 2;

    const float* Bsrc; int bstride;
    if (part == 0) { Bsrc = wkv + h * 256;             bstride = HH * 256; }
    else           { Bsrc = wuv + h * (LORAC * VDIMC); bstride = VDIMC;    }

    FragC acc[2][4];
    #pragma unroll
    for (int i = 0; i < 2; i++)
        #pragma unroll
        for (int j = 0; j < 4; j++) wmma::fill_fragment(acc[i][j], 0.f);

    for (int k0 = 0; k0 < LORAC; k0 += 32) {
        #pragma unroll
        for (int it = 0; it < 4; it++) {
            int i = tid + it * 256;
            int r = i >> 3, c4 = (i & 7) << 2;
            float4 v = tf32r4(*(const float4*)(kc + (size_t)(m0 + r) * LORAC + k0 + c4));
            *(float4*)&As[r * AS_LD + c4] = v;
        }
        #pragma unroll
        for (int it = 0; it < 4; it++) {
            int i = tid + it * 256;
            int k = i >> 5, n4 = (i & 31) << 2;
            float4 v = tf32r4(*(const float4*)(Bsrc + (size_t)(k0 + k) * bstride + n4));
            *(float4*)&Bs[k * BS_LD + n4] = v;
        }
        __syncthreads();

        #pragma unroll
        for (int ks = 0; ks < 4; ks++) {
            FragA a[2];
            FragBr b[4];
            #pragma unroll
            for (int i = 0; i < 2; i++)
                wmma::load_matrix_sync(a[i], As + (wr * 32 + 16 * i) * AS_LD + ks * 8, AS_LD);
            #pragma unroll
            for (int j = 0; j < 4; j++)
                wmma::load_matrix_sync(b[j], Bs + (ks * 8) * BS_LD + wc * 64 + 16 * j, BS_LD);
            #pragma unroll
            for (int i = 0; i < 2; i++)
                #pragma unroll
                for (int j = 0; j < 4; j++)
                    wmma::mma_sync(acc[i][j], a[i], b[j], acc[i][j]);
        }
        __syncthreads();
    }

    float* dst = (part == 0) ? (g_Kn + (size_t)h * TT * NOPEC) : (g_V + (size_t)h * TT * VDIMC);
    #pragma unroll
    for (int i = 0; i < 2; i++)
        #pragma unroll
        for (int j = 0; j < 4; j++) {
            #pragma unroll
            for (int e = 0; e < acc[i][j].num_elements; e++)
                acc[i][j].x[e] = tf32r(acc[i][j].x[e]);
            wmma::store_matrix_sync(dst + (size_t)(m0 + wr * 32 + 16 * i) * 128 + wc * 64 + 16 * j,
                                    acc[i][j], 128, wmma::mem_row_major);
        }
}

// Kernel 1b: pre-round rope once
__global__ void rope_round_kernel(const float* __restrict__ kpe)
{
    int i = blockIdx.x * blockDim.x + threadIdx.x;
    if (i >= TT * ROPEC / 4) return;
    ((float4*)g_rope)[i] = tf32r4(((const float4*)kpe)[i]);
}

// ---------------------------------------------------------------------------
// Kernel 2: wmma-tf32 causal flash attention.
//   BM=128, BN=64, 512 threads, warp grid 8(row)x2(col).
//   S warp tile 16x32, O warp tile 16x64. Q cols 0..63 in regs (aq[8]),
//   cols 64..191 in persistent smem. K single-buffered (sync load),
//   V cp.async double-buffered. Register exp, ones-MMA rowsum.
// ---------------------------------------------------------------------------
#define NTHR 512
#define KS_LD 200
#define VS_LD 132
#define PS_LD 68
#define QT_LD 132
#define LB_LD 20                                 // multiple of 4 (f32 wmma ldm req)
#define SM_K  0                                  // 64 x 200  = 51200 B
#define SM_V0 51200                              // 64 x 132  = 33792 B
#define SM_V1 84992                              // 64 x 132  = 33792 B
#define SM_PS 118784                             // 128 x 68  = 34816 B
#define SM_QT 153600                             // 128 x 132 = 67584 B
#define SM_LB 221184                             // 128 x 20  = 10240 B
#define FLASH_SMEM 231424

__global__ __launch_bounds__(NTHR) void flash_wmma(
    const float* __restrict__ q, float* __restrict__ out)
{
    const int bid = blockIdx.x;
    const int h = bid & 15, idx = bid >> 4;
    const int qt = (idx & 1) ? (idx >> 1) : (15 - (idx >> 1));  // heavy/light interleave

    extern __shared__ char smem[];
    const uint32_t sb = smem_u32(smem);
    float* Ks = (float*)(smem + SM_K);
    float* Ps = (float*)(smem + SM_PS);
    float* Qt = (float*)(smem + SM_QT);
    float* Lb = (float*)(smem + SM_LB);

    const int tid = threadIdx.x, wid = tid >> 5;
    const int wr = wid & 7, wc = wid >> 3;   // 8 row-groups (x16), 2 col-groups

    // ---- stage Q 128x192 into smem offset 0 (LD 200; spans K/V0/V1 region) ----
    {
        float* Qstage = (float*)(smem + SM_K);
        #pragma unroll
        for (int it = 0; it < 12; it++) {
            int i = tid + it * NTHR;             // 6144 float4
            int r = i / 48, c4 = (i % 48) * 4;
            float4 v = tf32r4(*(const float4*)(q + ((size_t)(qt * 128 + r) * HH + h) * DQK + c4));
            *(float4*)&Qstage[r * 200 + c4] = v;
        }
    }
    __syncthreads();

    // per-warp A-frags for Q cols 0..63; copy cols 64..191 to persistent Qt
    FragA aq[8];
    {
        float* Qstage = (float*)(smem + SM_K);
        #pragma unroll
        for (int ks = 0; ks < 8; ks++)
            wmma::load_matrix_sync(aq[ks], Qstage + (wr * 16) * 200 + ks * 8, 200);
        #pragma unroll
        for (int it = 0; it < 8; it++) {
            int i = tid + it * NTHR;             // 4096 float4 (128 x 128 cols)
            int r = i >> 5, c4 = (i & 31) << 2;
            *(float4*)&Qt[r * QT_LD + c4] = *(float4*)&Qstage[r * 200 + 64 + c4];
        }
    }
    __syncthreads();

    FragC oacc[4], osum;
    #pragma unroll
    for (int j = 0; j < 4; j++) wmma::fill_fragment(oacc[j], 0.f);
    wmma::fill_fragment(osum, 0.f);
    FragBr onesb;
    wmma::fill_fragment(onesb, 1.0f);

    const float* Knh = g_Kn + (size_t)h * TT * NOPEC;
    const float* Vh  = g_V  + (size_t)h * TT * VDIMC;
    const int njt = 2 * qt + 2;

    // prime V pipeline (buffer 0 region is free now — Q already consumed)
    {
        const uint32_t vb = sb + SM_V0;
        #pragma unroll
        for (int it = 0; it < 4; it++) {
            int i = tid + it * NTHR;
            int r = i >> 5, c4 = (i & 31) << 2;
            CP_ASYNC16(vb + (uint32_t)(r * VS_LD + c4) * 4, Vh + (size_t)r * VDIMC + c4);
        }
        CP_COMMIT();
    }

    for (int jt = 0; jt < njt; jt++) {
        // prefetch V(jt+1)
        if (jt < njt - 1) {
            const uint32_t vb = sb + (((jt + 1) & 1) ? SM_V1 : SM_V0);
            #pragma unroll
            for (int it = 0; it < 4; it++) {
                int i = tid + it * NTHR;
                int r = i >> 5, c4 = (i & 31) << 2;
                CP_ASYNC16(vb + (uint32_t)(r * VS_LD + c4) * 4,
                           Vh + (size_t)((jt + 1) * 64 + r) * VDIMC + c4);
            }
            CP_COMMIT();
        }
        // synchronous K tile load: 64 x (128 nope | 64 rope)
        #pragma unroll
        for (int it = 0; it < 4; it++) {
            int i = tid + it * NTHR;             // 2048 float4
            int r = i >> 5, c4 = (i & 31) << 2;
            *(float4*)&Ks[r * KS_LD + c4] =
                *(const float4*)(Knh + (size_t)(jt * 64 + r) * NOPEC + c4);
        }
        #pragma unroll
        for (int it = 0; it < 2; it++) {
            int i = tid + it * NTHR;             // 1024 float4
            int r = i >> 4, c4 = (i & 15) << 2;
            *(float4*)&Ks[r * KS_LD + NOPEC + c4] =
                *(const float4*)(g_rope + (size_t)(jt * 64 + r) * ROPEC + c4);
        }
        if (jt < njt - 1) { CP_WAIT(1); } else { CP_WAIT(0); }
        __syncthreads();

        float* Vs = (float*)(smem + ((jt & 1) ? SM_V1 : SM_V0));

        // ---- S = Q @ K^T (warp 16x32; aq regs for ks<8, Qt smem after) ----
        {
            FragC sacc[2];
            wmma::fill_fragment(sacc[0], 0.f);
            wmma::fill_fragment(sacc[1], 0.f);
            #pragma unroll
            for (int ks = 0; ks < 24; ks++) {
                FragA a;
                if (ks < 8) a = aq[ks];
                else wmma::load_matrix_sync(a, Qt + (wr * 16) * QT_LD + (ks * 8 - 64), QT_LD);
                FragBc b0, b1;
                wmma::load_matrix_sync(b0, Ks + (wc * 32) * KS_LD + ks * 8, KS_LD);
                wmma::load_matrix_sync(b1, Ks + (wc * 32 + 16) * KS_LD + ks * 8, KS_LD);
                wmma::mma_sync(sacc[0], a, b0, sacc[0]);
                wmma::mma_sync(sacc[1], a, b1, sacc[1]);
            }
            #pragma unroll
            for (int f = 0; f < 2; f++)
                #pragma unroll
                for (int e = 0; e < sacc[f].num_elements; e++)
                    sacc[f].x[e] = tf32r(__expf(sacc[f].x[e] * SCALE_F));
            wmma::store_matrix_sync(Ps + (wr * 16) * PS_LD + wc * 32,      sacc[0], PS_LD, wmma::mem_row_major);
            wmma::store_matrix_sync(Ps + (wr * 16) * PS_LD + wc * 32 + 16, sacc[1], PS_LD, wmma::mem_row_major);
        }
        __syncthreads();

        // ---- causal mask: tiles jt = 2qt and 2qt+1 are partially masked ----
        if (jt >= 2 * qt) {
            const int d = jt * 64 - qt * 128;    // 0 or 64
            const int srow = tid >> 2, scg = tid & 3;
            float* prow = Ps + srow * PS_LD + scg * 16;
            #pragma unroll
            for (int c = 0; c < 16; c++)
                if (d + scg * 16 + c > srow) prow[c] = 0.f;
            __syncthreads();
        }

        // ---- O += P @ V (warp 16x64); osum += P @ ones (wc==0) ----
        #pragma unroll
        for (int ks = 0; ks < 8; ks++) {
            FragA a;
            wmma::load_matrix_sync(a, Ps + (wr * 16) * PS_LD + ks * 8, PS_LD);
            #pragma unroll
            for (int j = 0; j < 4; j++) {
                FragBr b;
                wmma::load_matrix_sync(b, Vs + (ks * 8) * VS_LD + wc * 64 + 16 * j, VS_LD);
                wmma::mma_sync(oacc[j], a, b, oacc[j]);
            }
            if (wc == 0) wmma::mma_sync(osum, a, onesb, osum);
        }
        __syncthreads();
    }

    // ---- row sums (all cols of osum identical; read col 0) ----
    if (wc == 0)
        wmma::store_matrix_sync(Lb + wr * 16 * LB_LD, osum, LB_LD, wmma::mem_row_major);
    // ---- stage O 128x128 at offset 0 (K/V region, all consumed) ----
    float* Os = (float*)(smem + SM_K);
    #pragma unroll
    for (int j = 0; j < 4; j++)
        wmma::store_matrix_sync(Os + (wr * 16) * VS_LD + wc * 64 + 16 * j,
                                oacc[j], VS_LD, wmma::mem_row_major);
    __syncthreads();

    #pragma unroll
    for (int it = 0; it < 8; it++) {
        int i = tid + it * NTHR;                 // 4096 float4
        int r = i >> 5, c4 = (i & 31) << 2;
        float inv = 1.f / Lb[r * LB_LD];
        float4 v = *(float4*)&Os[r * VS_LD + c4];
        *(float4*)(out + (size_t)(qt * 128 + r) * (HH * VDIMC) + h * VDIMC + c4) =
            make_float4(v.x * inv, v.y * inv, v.z * inv, v.w * inv);
    }
}

// ---------------------------------------------------------------------------
extern "C" void kernel_launch(void* const* d_in, const int* in_sizes, int n_in,
                              void* d_out, int out_size)
{
    (void)in_sizes; (void)n_in; (void)out_size;
    const float* q   = (const float*)d_in[0];   // (T, H, 192)
    const float* kc  = (const float*)d_in[1];   // (T, 512)
    const float* kpe = (const float*)d_in[2];   // (T, 64)
    const float* wkv = (const float*)d_in[3];   // (512, 4096)
    const float* wuv = (const float*)d_in[4];   // (16, 512, 128)
    float* out = (float*)d_out;                 // (T, 2048)

    cudaFuncSetAttribute(flash_wmma, cudaFuncAttributeMaxDynamicSharedMemorySize, FLASH_SMEM);

    dim3 g1(TT / 128, 2, HH);
    kv_gemm_wmma<<<g1, 256>>>(kc, wkv, wuv);
    rope_round_kernel<<<(TT * ROPEC / 4 + 255) / 256, 256>>>(kpe);

    flash_wmma<<<(TT / 128) * HH, NTHR, FLASH_SMEM>>>(q, out);
}

// round 14
// speedup vs baseline: 2.6765x; 2.5418x over previous
#include <cuda_runtime.h>
#include <cuda_fp16.h>
#include <mma.h>
#include <math.h>
#include <stdint.h>

using namespace nvcuda;

#define HH 16
#define TT 2048
#define DQK 192
#define NOPEC 128
#define ROPEC 64
#define LORAC 512
#define VDIMC 128
#define SCALE_F 0.07216878364870323f   // 1/sqrt(192)

// Device scratch (no allocation allowed), 16B-aligned for cp.async/float4
__device__ __align__(16) __half g_Kn[HH * TT * NOPEC];   // per-head k_nope, fp16
__device__ __align__(16) __half g_V [HH * TT * VDIMC];   // absorbed V_h, fp16
__device__ __align__(16) __half g_rope[TT * ROPEC];      // k_pe, fp16

__device__ __forceinline__ uint32_t smem_u32(const void* p) {
    uint32_t a;
    asm("{ .reg .u64 t; cvta.to.shared.u64 t, %1; cvt.u32.u64 %0, t; }" : "=r"(a) : "l"(p));
    return a;
}
// convert float4 -> 4 halfs packed in uint2
__device__ __forceinline__ uint2 f4_to_h4(float4 v) {
    __half2 lo = __floats2half2_rn(v.x, v.y);
    __half2 hi = __floats2half2_rn(v.z, v.w);
    uint2 r;
    r.x = *(uint32_t*)&lo;
    r.y = *(uint32_t*)&hi;
    return r;
}
#define CP_ASYNC16(saddr, gptr) \
    asm volatile("cp.async.cg.shared.global [%0], [%1], 16;" :: "r"(saddr), "l"(gptr))
#define CP_COMMIT() asm volatile("cp.async.commit_group;" ::: "memory")
#define CP_WAIT(n)  asm volatile("cp.async.wait_group %0;" :: "n"(n) : "memory")

typedef wmma::fragment<wmma::matrix_a, 16, 16, 16, __half, wmma::row_major> FragA;
typedef wmma::fragment<wmma::matrix_b, 16, 16, 16, __half, wmma::row_major> FragBr;
typedef wmma::fragment<wmma::matrix_b, 16, 16, 16, __half, wmma::col_major> FragBc;
typedef wmma::fragment<wmma::accumulator, 16, 16, 16, float> FragC;

// ---------------------------------------------------------------------------
// Kernel 1: fp16 prep GEMM (BK=32). fp32 accumulate; outputs stored fp16.
//   part 0: k_nope[h] ; part 1: V_h. Epilogue stages f32 in smem, converts.
// ---------------------------------------------------------------------------
#define AS_LD 40                                 // halfs; mult of 8
#define BS_LD 136                                // halfs; mult of 8
#define ST_LD 132                                // f32 staging ld; mult of 4

__global__ __launch_bounds__(256) void kv_gemm_wmma(
    const float* __restrict__ kc, const float* __restrict__ wkv, const float* __restrict__ wuv)
{
    const int m0 = blockIdx.x * 128, part = blockIdx.y, h = blockIdx.z;
    // union: As(128*40 halfs)+Bs(32*136 halfs) = 18944B  |  staging 64*132 f32 = 33792B
    __shared__ __align__(16) char smraw[33792];
    __half* As = (__half*)smraw;
    __half* Bs = (__half*)smraw + 128 * AS_LD;
    float*  Stg = (float*)smraw;

    const int tid = threadIdx.x, wid = tid >> 5;
    const int wr = wid & 3, wc = wid >> 2;

    const float* Bsrc; int bstride;
    if (part == 0) { Bsrc = wkv + h * 256;             bstride = HH * 256; }
    else           { Bsrc = wuv + h * (LORAC * VDIMC); bstride = VDIMC;    }

    FragC acc[2][4];
    #pragma unroll
    for (int i = 0; i < 2; i++)
        #pragma unroll
        for (int j = 0; j < 4; j++) wmma::fill_fragment(acc[i][j], 0.f);

    for (int k0 = 0; k0 < LORAC; k0 += 32) {
        #pragma unroll
        for (int it = 0; it < 4; it++) {
            int i = tid + it * 256;              // 1024 float4 over A 128x32
            int r = i >> 3, c4 = (i & 7) << 2;
            float4 v = *(const float4*)(kc + (size_t)(m0 + r) * LORAC + k0 + c4);
            *(uint2*)&As[r * AS_LD + c4] = f4_to_h4(v);
        }
        #pragma unroll
        for (int it = 0; it < 4; it++) {
            int i = tid + it * 256;              // 1024 float4 over B 32x128
            int k = i >> 5, n4 = (i & 31) << 2;
            float4 v = *(const float4*)(Bsrc + (size_t)(k0 + k) * bstride + n4);
            *(uint2*)&Bs[k * BS_LD + n4] = f4_to_h4(v);
        }
        __syncthreads();

        #pragma unroll
        for (int ks = 0; ks < 2; ks++) {
            FragA a[2];
            FragBr b[4];
            #pragma unroll
            for (int i = 0; i < 2; i++)
                wmma::load_matrix_sync(a[i], As + (wr * 32 + 16 * i) * AS_LD + ks * 16, AS_LD);
            #pragma unroll
            for (int j = 0; j < 4; j++)
                wmma::load_matrix_sync(b[j], Bs + (ks * 16) * BS_LD + wc * 64 + 16 * j, BS_LD);
            #pragma unroll
            for (int i = 0; i < 2; i++)
                #pragma unroll
                for (int j = 0; j < 4; j++)
                    wmma::mma_sync(acc[i][j], a[i], b[j], acc[i][j]);
        }
        __syncthreads();
    }

    __half* dst = (part == 0) ? (g_Kn + (size_t)h * TT * NOPEC) : (g_V + (size_t)h * TT * VDIMC);
    // epilogue: two passes of 64 rows through f32 staging, convert to fp16
    #pragma unroll
    for (int p = 0; p < 2; p++) {
        __syncthreads();
        if ((wr >> 1) == p) {
            #pragma unroll
            for (int i = 0; i < 2; i++)
                #pragma unroll
                for (int j = 0; j < 4; j++)
                    wmma::store_matrix_sync(
                        Stg + ((wr & 1) * 32 + 16 * i) * ST_LD + wc * 64 + 16 * j,
                        acc[i][j], ST_LD, wmma::mem_row_major);
        }
        __syncthreads();
        #pragma unroll
        for (int it = 0; it < 8; it++) {
            int i = tid + it * 256;              // 2048 chunks of 4 over 64x128
            int r = i >> 5, c4 = (i & 31) << 2;
            float4 v = *(float4*)&Stg[r * ST_LD + c4];
            *(uint2*)(dst + (size_t)(m0 + 64 * p + r) * 128 + c4) = f4_to_h4(v);
        }
    }
}

// Kernel 1b: rope -> fp16
__global__ void rope_h_kernel(const float* __restrict__ kpe)
{
    int i = blockIdx.x * blockDim.x + threadIdx.x;   // float4 index over T*64
    if (i >= TT * ROPEC / 4) return;
    float4 v = ((const float4*)kpe)[i];
    *(uint2*)(g_rope + i * 4) = f4_to_h4(v);
}

// ---------------------------------------------------------------------------
// Kernel 2: fp16 wmma causal flash attention.
//   BM=BN=64, 256 thr, 8 warps (4 row x 2 col). Q entirely in registers
//   (12 fp16 A-frags = 48 regs). K+V double-buffered cp.async.
//   S in f32 acc -> smem f32 -> softmax pass (exp+mask+rowsum+fp16 P).
// ---------------------------------------------------------------------------
#define KS_LD 200                                // halfs; mult of 8
#define VS_LD 136                                // halfs
#define PSF_LD 68                                // f32
#define PSH_LD 72                                // halfs
#define KT_B (64 * KS_LD * 2)                    // 25600
#define VT_B (64 * VS_LD * 2)                    // 17408
#define SM_K0 0
#define SM_K1 KT_B                               // 25600
#define SM_V0 (2 * KT_B)                         // 51200
#define SM_V1 (2 * KT_B + VT_B)                  // 68608
#define SM_PF (2 * KT_B + 2 * VT_B)              // 86016 (64*68*4 = 17408)
#define SM_PH (SM_PF + 64 * PSF_LD * 4)          // 103424 (64*72*2 = 9216)
#define SM_LS (SM_PH + 64 * PSH_LD * 2)          // 112640
#define FLASH_SMEM (SM_LS + 64 * 4)              // 112896

__device__ __forceinline__ void prefetch_tile(
    uint32_t sb, int buf, int jt, int tid,
    const __half* __restrict__ Knh, const __half* __restrict__ Vh)
{
    const uint32_t kb = sb + (buf ? SM_K1 : SM_K0);
    const uint32_t vb = sb + (buf ? SM_V1 : SM_V0);
    #pragma unroll
    for (int it = 0; it < 4; it++) {
        int i = tid + it * 256;                  // 1024 chunks (K nope: 64 x 256B)
        int r = i >> 4, c = i & 15;
        CP_ASYNC16(kb + (uint32_t)(r * KS_LD + c * 8) * 2,
                   Knh + (size_t)(jt * 64 + r) * NOPEC + c * 8);
    }
    #pragma unroll
    for (int it = 0; it < 2; it++) {
        int i = tid + it * 256;                  // 512 chunks (rope: 64 x 128B)
        int r = i >> 3, c = i & 7;
        CP_ASYNC16(kb + (uint32_t)(r * KS_LD + NOPEC + c * 8) * 2,
                   g_rope + (size_t)(jt * 64 + r) * ROPEC + c * 8);
    }
    #pragma unroll
    for (int it = 0; it < 4; it++) {
        int i = tid + it * 256;                  // 1024 chunks (V: 64 x 256B)
        int r = i >> 4, c = i & 15;
        CP_ASYNC16(vb + (uint32_t)(r * VS_LD + c * 8) * 2,
                   Vh + (size_t)(jt * 64 + r) * VDIMC + c * 8);
    }
    CP_COMMIT();
}

__global__ __launch_bounds__(256) void flash_wmma(
    const float* __restrict__ q, float* __restrict__ out)
{
    const int bid = blockIdx.x;
    const int h = bid & 15, idx = bid >> 4;
    const int qt = (idx & 1) ? (idx >> 1) : (31 - (idx >> 1));  // heavy/light interleave

    extern __shared__ char smem[];
    const uint32_t sb = smem_u32(smem);
    float*  Pf = (float*)(smem + SM_PF);
    __half* Ph = (__half*)(smem + SM_PH);
    float*  Ls = (float*)(smem + SM_LS);

    const int tid = threadIdx.x, wid = tid >> 5;
    const int wr = wid & 3, wc = wid >> 2;   // warp row (x16), warp col (x32)

    // ---- stage Q 64x192 (fp16) into K0 buffer, preload 12 A-frags ----
    {
        __half* Qs = (__half*)(smem + SM_K0);
        #pragma unroll
        for (int it = 0; it < 12; it++) {
            int i = tid + it * 256;              // 3072 float4
            int r = i / 48, c4 = (i % 48) * 4;
            float4 v = *(const float4*)(q + ((size_t)(qt * 64 + r) * HH + h) * DQK + c4);
            *(uint2*)&Qs[r * KS_LD + c4] = f4_to_h4(v);
        }
    }
    __syncthreads();

    FragA aq[12];
    #pragma unroll
    for (int ks = 0; ks < 12; ks++)
        wmma::load_matrix_sync(aq[ks], (__half*)(smem + SM_K0) + (wr * 16) * KS_LD + ks * 16, KS_LD);
    __syncthreads();

    FragC oacc[4];
    #pragma unroll
    for (int j = 0; j < 4; j++) wmma::fill_fragment(oacc[j], 0.f);

    const int srow = tid >> 2;               // softmax row (0..63)
    const int scg  = tid & 3;                // 16-col group
    float lsum = 0.f;

    const __half* Knh = g_Kn + (size_t)h * TT * NOPEC;
    const __half* Vh  = g_V  + (size_t)h * TT * VDIMC;

    prefetch_tile(sb, 0, 0, tid, Knh, Vh);

    for (int jt = 0; jt <= qt; jt++) {
        if (jt < qt) {
            prefetch_tile(sb, (jt + 1) & 1, jt + 1, tid, Knh, Vh);
            CP_WAIT(1);
        } else {
            CP_WAIT(0);
        }
        __syncthreads();

        __half* Ks = (__half*)(smem + ((jt & 1) ? SM_K1 : SM_K0));
        __half* Vs = (__half*)(smem + ((jt & 1) ? SM_V1 : SM_V0));

        // ---- S = Q @ K^T (warp 16x32; 12 k-steps of 16) ----
        {
            FragC sacc[2];
            wmma::fill_fragment(sacc[0], 0.f);
            wmma::fill_fragment(sacc[1], 0.f);
            #pragma unroll
            for (int ks = 0; ks < 12; ks++) {
                FragBc b0, b1;
                wmma::load_matrix_sync(b0, Ks + (wc * 32) * KS_LD + ks * 16, KS_LD);
                wmma::load_matrix_sync(b1, Ks + (wc * 32 + 16) * KS_LD + ks * 16, KS_LD);
                wmma::mma_sync(sacc[0], aq[ks], b0, sacc[0]);
                wmma::mma_sync(sacc[1], aq[ks], b1, sacc[1]);
            }
            wmma::store_matrix_sync(Pf + (wr * 16) * PSF_LD + wc * 32,      sacc[0], PSF_LD, wmma::mem_row_major);
            wmma::store_matrix_sync(Pf + (wr * 16) * PSF_LD + wc * 32 + 16, sacc[1], PSF_LD, wmma::mem_row_major);
        }
        __syncthreads();

        // ---- softmax pass: exp + causal mask + rowsum + fp16 P ----
        {
            const int gr = qt * 64 + srow;
            const int jc0 = jt * 64 + scg * 16;
            const float* prow = Pf + srow * PSF_LD + scg * 16;
            __half* hrow = Ph + srow * PSH_LD + scg * 16;
            #pragma unroll
            for (int c = 0; c < 16; c += 2) {
                float s0 = prow[c], s1 = prow[c + 1];
                float p0 = (jc0 + c     <= gr) ? __expf(s0 * SCALE_F) : 0.f;
                float p1 = (jc0 + c + 1 <= gr) ? __expf(s1 * SCALE_F) : 0.f;
                __half2 hp = __floats2half2_rn(p0, p1);
                lsum += __low2float(hp) + __high2float(hp);   // sum what P actually is
                *(__half2*)(hrow + c) = hp;
            }
        }
        __syncthreads();

        // ---- O += P @ V (warp 16x64; 4 k-steps of 16) ----
        #pragma unroll
        for (int ks = 0; ks < 4; ks++) {
            FragA a;
            wmma::load_matrix_sync(a, Ph + (wr * 16) * PSH_LD + ks * 16, PSH_LD);
            #pragma unroll
            for (int j = 0; j < 4; j++) {
                FragBr b;
                wmma::load_matrix_sync(b, Vs + (ks * 16) * VS_LD + wc * 64 + 16 * j, VS_LD);
                wmma::mma_sync(oacc[j], a, b, oacc[j]);
            }
        }
        __syncthreads();
    }

    // ---- row-sum reduce (4 threads per row) ----
    lsum += __shfl_xor_sync(0xffffffffu, lsum, 1);
    lsum += __shfl_xor_sync(0xffffffffu, lsum, 2);
    if (scg == 0) Ls[srow] = 1.f / lsum;

    // ---- stage O (f32) at offset 0 (K buffers consumed), normalize, store ----
    float* Os = (float*)(smem + SM_K0);          // 64 x 132 f32 = 33792 <= 51200
    #pragma unroll
    for (int j = 0; j < 4; j++)
        wmma::store_matrix_sync(Os + (wr * 16) * 132 + wc * 64 + 16 * j,
                                oacc[j], 132, wmma::mem_row_major);
    __syncthreads();

    #pragma unroll
    for (int it = 0; it < 8; it++) {
        int i = tid + it * 256;                  // 2048 float4
        int r = i >> 5, c4 = (i & 31) << 2;
        float inv = Ls[r];
        float4 v = *(float4*)&Os[r * 132 + c4];
        *(float4*)(out + (size_t)(qt * 64 + r) * (HH * VDIMC) + h * VDIMC + c4) =
            make_float4(v.x * inv, v.y * inv, v.z * inv, v.w * inv);
    }
}

// ---------------------------------------------------------------------------
extern "C" void kernel_launch(void* const* d_in, const int* in_sizes, int n_in,
                              void* d_out, int out_size)
{
    (void)in_sizes; (void)n_in; (void)out_size;
    const float* q   = (const float*)d_in[0];   // (T, H, 192)
    const float* kc  = (const float*)d_in[1];   // (T, 512)
    const float* kpe = (const float*)d_in[2];   // (T, 64)
    const float* wkv = (const float*)d_in[3];   // (512, 4096)
    const float* wuv = (const float*)d_in[4];   // (16, 512, 128)
    float* out = (float*)d_out;                 // (T, 2048)

    cudaFuncSetAttribute(flash_wmma, cudaFuncAttributeMaxDynamicSharedMemorySize, FLASH_SMEM);

    dim3 g1(TT / 128, 2, HH);
    kv_gemm_wmma<<<g1, 256>>>(kc, wkv, wuv);
    rope_h_kernel<<<(TT * ROPEC / 4 + 255) / 256, 256>>>(kpe);

    flash_wmma<<<(TT / 64) * HH, 256, FLASH_SMEM>>>(q, out);
}

// round 16
// speedup vs baseline: 3.7675x; 1.4076x over previous
#include <cuda_runtime.h>
#include <cuda_fp16.h>
#include <mma.h>
#include <math.h>
#include <stdint.h>

using namespace nvcuda;

#define HH 16
#define TT 2048
#define DQK 192
#define NOPEC 128
#define ROPEC 64
#define LORAC 512
#define VDIMC 128
#define SCALE_F 0.07216878364870323f   // 1/sqrt(192)

// Device scratch (no allocation allowed), 16B-aligned for cp.async/float4
__device__ __align__(16) __half g_Kn[HH * TT * NOPEC];   // per-head k_nope, fp16
__device__ __align__(16) __half g_V [HH * TT * VDIMC];   // absorbed V_h, fp16
__device__ __align__(16) __half g_rope[TT * ROPEC];      // k_pe, fp16

__device__ __forceinline__ uint32_t smem_u32(const void* p) {
    uint32_t a;
    asm("{ .reg .u64 t; cvta.to.shared.u64 t, %1; cvt.u32.u64 %0, t; }" : "=r"(a) : "l"(p));
    return a;
}
__device__ __forceinline__ uint2 f4_to_h4(float4 v) {
    __half2 lo = __floats2half2_rn(v.x, v.y);
    __half2 hi = __floats2half2_rn(v.z, v.w);
    uint2 r;
    r.x = *(uint32_t*)&lo;
    r.y = *(uint32_t*)&hi;
    return r;
}
#define CP_ASYNC16(saddr, gptr) \
    asm volatile("cp.async.cg.shared.global [%0], [%1], 16;" :: "r"(saddr), "l"(gptr))
#define CP_COMMIT() asm volatile("cp.async.commit_group;" ::: "memory")
#define CP_WAIT(n)  asm volatile("cp.async.wait_group %0;" :: "n"(n) : "memory")

typedef wmma::fragment<wmma::matrix_a, 16, 16, 16, __half, wmma::row_major> FragA;
typedef wmma::fragment<wmma::matrix_b, 16, 16, 16, __half, wmma::row_major> FragBr;
typedef wmma::fragment<wmma::matrix_b, 16, 16, 16, __half, wmma::col_major> FragBc;
typedef wmma::fragment<wmma::accumulator, 16, 16, 16, float> FragC;

// ---------------------------------------------------------------------------
// Kernel 1: fp16 prep GEMM (unchanged from R14 — 71.3us).
// ---------------------------------------------------------------------------
#define AS_LD 40
#define BS_LD 136
#define ST_LD 132

__global__ __launch_bounds__(256) void kv_gemm_wmma(
    const float* __restrict__ kc, const float* __restrict__ wkv, const float* __restrict__ wuv)
{
    const int m0 = blockIdx.x * 128, part = blockIdx.y, h = blockIdx.z;
    __shared__ __align__(16) char smraw[33792];
    __half* As = (__half*)smraw;
    __half* Bs = (__half*)smraw + 128 * AS_LD;
    float*  Stg = (float*)smraw;

    const int tid = threadIdx.x, wid = tid >> 5;
    const int wr = wid & 3, wc = wid >> 2;

    const float* Bsrc; int bstride;
    if (part == 0) { Bsrc = wkv + h * 256;             bstride = HH * 256; }
    else           { Bsrc = wuv + h * (LORAC * VDIMC); bstride = VDIMC;    }

    FragC acc[2][4];
    #pragma unroll
    for (int i = 0; i < 2; i++)
        #pragma unroll
        for (int j = 0; j < 4; j++) wmma::fill_fragment(acc[i][j], 0.f);

    for (int k0 = 0; k0 < LORAC; k0 += 32) {
        #pragma unroll
        for (int it = 0; it < 4; it++) {
            int i = tid + it * 256;
            int r = i >> 3, c4 = (i & 7) << 2;
            float4 v = *(const float4*)(kc + (size_t)(m0 + r) * LORAC + k0 + c4);
            *(uint2*)&As[r * AS_LD + c4] = f4_to_h4(v);
        }
        #pragma unroll
        for (int it = 0; it < 4; it++) {
            int i = tid + it * 256;
            int k = i >> 5, n4 = (i & 31) << 2;
            float4 v = *(const float4*)(Bsrc + (size_t)(k0 + k) * bstride + n4);
            *(uint2*)&Bs[k * BS_LD + n4] = f4_to_h4(v);
        }
        __syncthreads();

        #pragma unroll
        for (int ks = 0; ks < 2; ks++) {
            FragA a[2];
            FragBr b[4];
            #pragma unroll
            for (int i = 0; i < 2; i++)
                wmma::load_matrix_sync(a[i], As + (wr * 32 + 16 * i) * AS_LD + ks * 16, AS_LD);
            #pragma unroll
            for (int j = 0; j < 4; j++)
                wmma::load_matrix_sync(b[j], Bs + (ks * 16) * BS_LD + wc * 64 + 16 * j, BS_LD);
            #pragma unroll
            for (int i = 0; i < 2; i++)
                #pragma unroll
                for (int j = 0; j < 4; j++)
                    wmma::mma_sync(acc[i][j], a[i], b[j], acc[i][j]);
        }
        __syncthreads();
    }

    __half* dst = (part == 0) ? (g_Kn + (size_t)h * TT * NOPEC) : (g_V + (size_t)h * TT * VDIMC);
    #pragma unroll
    for (int p = 0; p < 2; p++) {
        __syncthreads();
        if ((wr >> 1) == p) {
            #pragma unroll
            for (int i = 0; i < 2; i++)
                #pragma unroll
                for (int j = 0; j < 4; j++)
                    wmma::store_matrix_sync(
                        Stg + ((wr & 1) * 32 + 16 * i) * ST_LD + wc * 64 + 16 * j,
                        acc[i][j], ST_LD, wmma::mem_row_major);
        }
        __syncthreads();
        #pragma unroll
        for (int it = 0; it < 8; it++) {
            int i = tid + it * 256;
            int r = i >> 5, c4 = (i & 31) << 2;
            float4 v = *(float4*)&Stg[r * ST_LD + c4];
            *(uint2*)(dst + (size_t)(m0 + 64 * p + r) * 128 + c4) = f4_to_h4(v);
        }
    }
}

// Kernel 1b: rope -> fp16
__global__ void rope_h_kernel(const float* __restrict__ kpe)
{
    int i = blockIdx.x * blockDim.x + threadIdx.x;
    if (i >= TT * ROPEC / 4) return;
    float4 v = ((const float4*)kpe)[i];
    *(uint2*)(g_rope + i * 4) = f4_to_h4(v);
}

// ---------------------------------------------------------------------------
// Kernel 2: fp16 wmma causal flash attention, BM=128, BN=64, 512 threads.
//   Warp grid 8(row)x2(col): S warp tile 16x32, O warp tile 16x64.
//   Q cols 0..127 in regs (aq[8]), cols 128..191 in persistent smem.
//   K and V cp.async double-buffered.
// ---------------------------------------------------------------------------
#define NTHR 512
#define KS_LD 200                                // halfs
#define VS_LD 136                                // halfs
#define PSF_LD 68                                // f32
#define PSH_LD 72                                // halfs
#define QT_LD 72                                 // halfs (64 data cols + pad)
#define KT_B (64 * KS_LD * 2)                    // 25600
#define VT_B (64 * VS_LD * 2)                    // 17408
#define SM_K0 0
#define SM_K1 KT_B                               // 25600
#define SM_V0 (2 * KT_B)                         // 51200
#define SM_V1 (2 * KT_B + VT_B)                  // 68608
#define SM_PF (2 * KT_B + 2 * VT_B)              // 86016  (128*68*4 = 34816)
#define SM_PH (SM_PF + 128 * PSF_LD * 4)         // 120832 (128*72*2 = 18432)
#define SM_QT (SM_PH + 128 * PSH_LD * 2)         // 139264 (128*72*2 = 18432)
#define SM_LS (SM_QT + 128 * QT_LD * 2)          // 157696 (128*4 = 512)
#define FLASH_SMEM (SM_LS + 128 * 4)             // 158208

__device__ __forceinline__ void prefetch_tile(
    uint32_t sb, int buf, int jt, int tid,
    const __half* __restrict__ Knh, const __half* __restrict__ Vh)
{
    const uint32_t kb = sb + (buf ? SM_K1 : SM_K0);
    const uint32_t vb = sb + (buf ? SM_V1 : SM_V0);
    #pragma unroll
    for (int it = 0; it < 2; it++) {
        int i = tid + it * NTHR;                 // 1024 chunks (K nope 64x256B)
        int r = i >> 4, c = i & 15;
        CP_ASYNC16(kb + (uint32_t)(r * KS_LD + c * 8) * 2,
                   Knh + (size_t)(jt * 64 + r) * NOPEC + c * 8);
    }
    {
        int i = tid;                             // 512 chunks (rope 64x128B)
        int r = i >> 3, c = i & 7;
        CP_ASYNC16(kb + (uint32_t)(r * KS_LD + NOPEC + c * 8) * 2,
                   g_rope + (size_t)(jt * 64 + r) * ROPEC + c * 8);
    }
    #pragma unroll
    for (int it = 0; it < 2; it++) {
        int i = tid + it * NTHR;                 // 1024 chunks (V 64x256B)
        int r = i >> 4, c = i & 15;
        CP_ASYNC16(vb + (uint32_t)(r * VS_LD + c * 8) * 2,
                   Vh + (size_t)(jt * 64 + r) * VDIMC + c * 8);
    }
    CP_COMMIT();
}

__global__ __launch_bounds__(NTHR) void flash_wmma(
    const float* __restrict__ q, float* __restrict__ out)
{
    const int bid = blockIdx.x;
    const int h = bid & 15, idx = bid >> 4;
    const int qt = (idx & 1) ? (idx >> 1) : (15 - (idx >> 1));  // heavy/light interleave

    extern __shared__ char smem[];
    const uint32_t sb = smem_u32(smem);
    float*  Pf = (float*)(smem + SM_PF);
    __half* Ph = (__half*)(smem + SM_PH);
    __half* Qt = (__half*)(smem + SM_QT);
    float*  Ls = (float*)(smem + SM_LS);

    const int tid = threadIdx.x, wid = tid >> 5;
    const int wr = wid & 7, wc = wid >> 3;   // 8 row-groups (x16), 2 col-groups

    // ---- stage Q 128x192 (fp16) into K0+K1 region (128*200h = 51200B) ----
    {
        __half* Qs = (__half*)(smem + SM_K0);
        #pragma unroll
        for (int it = 0; it < 12; it++) {
            int i = tid + it * NTHR;             // 6144 float4
            int r = i / 48, c4 = (i % 48) * 4;
            float4 v = *(const float4*)(q + ((size_t)(qt * 128 + r) * HH + h) * DQK + c4);
            *(uint2*)&Qs[r * KS_LD + c4] = f4_to_h4(v);
        }
    }
    __syncthreads();

    // aq[8]: Q cols 0..127 in regs; cols 128..191 -> persistent Qt
    FragA aq[8];
    {
        __half* Qs = (__half*)(smem + SM_K0);
        #pragma unroll
        for (int ks = 0; ks < 8; ks++)
            wmma::load_matrix_sync(aq[ks], Qs + (wr * 16) * KS_LD + ks * 16, KS_LD);
        #pragma unroll
        for (int it = 0; it < 2; it++) {
            int i = tid + it * NTHR;             // 1024 uint4 (128 rows x 64 cols; 8 halfs each)
            int r = i >> 3, c8 = (i & 7) << 3;
            *(uint4*)&Qt[r * QT_LD + c8] = *(uint4*)&Qs[r * KS_LD + 128 + c8];
        }
    }
    __syncthreads();

    FragC oacc[4];
    #pragma unroll
    for (int j = 0; j < 4; j++) wmma::fill_fragment(oacc[j], 0.f);

    const int srow = tid >> 2;               // softmax row (0..127)
    const int scg  = tid & 3;                // 16-col group
    float lsum = 0.f;

    const __half* Knh = g_Kn + (size_t)h * TT * NOPEC;
    const __half* Vh  = g_V  + (size_t)h * TT * VDIMC;
    const int njt = 2 * qt + 2;

    prefetch_tile(sb, 0, 0, tid, Knh, Vh);

    for (int jt = 0; jt < njt; jt++) {
        if (jt < njt - 1) {
            prefetch_tile(sb, (jt + 1) & 1, jt + 1, tid, Knh, Vh);
            CP_WAIT(1);
        } else {
            CP_WAIT(0);
        }
        __syncthreads();

        __half* Ks = (__half*)(smem + ((jt & 1) ? SM_K1 : SM_K0));
        __half* Vs = (__half*)(smem + ((jt & 1) ? SM_V1 : SM_V0));

        // ---- S = Q @ K^T (warp 16x32; 12 k-steps of 16) ----
        {
            FragC sacc[2];
            wmma::fill_fragment(sacc[0], 0.f);
            wmma::fill_fragment(sacc[1], 0.f);
            #pragma unroll
            for (int ks = 0; ks < 12; ks++) {
                FragA a;
                if (ks < 8) a = aq[ks];
                else wmma::load_matrix_sync(a, Qt + (wr * 16) * QT_LD + (ks * 16 - 128), QT_LD);
                FragBc b0, b1;
                wmma::load_matrix_sync(b0, Ks + (wc * 32) * KS_LD + ks * 16, KS_LD);
                wmma::load_matrix_sync(b1, Ks + (wc * 32 + 16) * KS_LD + ks * 16, KS_LD);
                wmma::mma_sync(sacc[0], a, b0, sacc[0]);
                wmma::mma_sync(sacc[1], a, b1, sacc[1]);
            }
            wmma::store_matrix_sync(Pf + (wr * 16) * PSF_LD + wc * 32,      sacc[0], PSF_LD, wmma::mem_row_major);
            wmma::store_matrix_sync(Pf + (wr * 16) * PSF_LD + wc * 32 + 16, sacc[1], PSF_LD, wmma::mem_row_major);
        }
        __syncthreads();

        // ---- softmax pass: exp + causal mask + rowsum + fp16 P ----
        {
            const int gr = srow;                       // local row == global row - qt*128
            const int d = jt * 64 - qt * 128;          // col offset of this tile vs q rows
            const int jc0 = d + scg * 16;
            const float* prow = Pf + srow * PSF_LD + scg * 16;
            __half* hrow = Ph + srow * PSH_LD + scg * 16;
            #pragma unroll
            for (int c = 0; c < 16; c += 2) {
                float s0 = prow[c], s1 = prow[c + 1];
                float p0 = (jc0 + c     <= gr) ? __expf(s0 * SCALE_F) : 0.f;
                float p1 = (jc0 + c + 1 <= gr) ? __expf(s1 * SCALE_F) : 0.f;
                __half2 hp = __floats2half2_rn(p0, p1);
                lsum += __low2float(hp) + __high2float(hp);
                *(__half2*)(hrow + c) = hp;
            }
        }
        __syncthreads();

        // ---- O += P @ V (warp 16x64; 4 k-steps of 16) ----
        #pragma unroll
        for (int ks = 0; ks < 4; ks++) {
            FragA a;
            wmma::load_matrix_sync(a, Ph + (wr * 16) * PSH_LD + ks * 16, PSH_LD);
            #pragma unroll
            for (int j = 0; j < 4; j++) {
                FragBr b;
                wmma::load_matrix_sync(b, Vs + (ks * 16) * VS_LD + wc * 64 + 16 * j, VS_LD);
                wmma::mma_sync(oacc[j], a, b, oacc[j]);
            }
        }
        __syncthreads();
    }

    // ---- row-sum reduce (4 threads per row) ----
    lsum += __shfl_xor_sync(0xffffffffu, lsum, 1);
    lsum += __shfl_xor_sync(0xffffffffu, lsum, 2);
    if (scg == 0) Ls[srow] = 1.f / lsum;

    // ---- stage O (f32, 128x132) at offset 0 (K+V0 regions consumed) ----
    float* Os = (float*)(smem + SM_K0);          // 128*132*4 = 67584 <= 68608
    #pragma unroll
    for (int j = 0; j < 4; j++)
        wmma::store_matrix_sync(Os + (wr * 16) * 132 + wc * 64 + 16 * j,
                                oacc[j], 132, wmma::mem_row_major);
    __syncthreads();

    #pragma unroll
    for (int it = 0; it < 8; it++) {
        int i = tid + it * NTHR;                 // 4096 float4
        int r = i >> 5, c4 = (i & 31) << 2;
        float inv = Ls[r];
        float4 v = *(float4*)&Os[r * 132 + c4];
        *(float4*)(out + (size_t)(qt * 128 + r) * (HH * VDIMC) + h * VDIMC + c4) =
            make_float4(v.x * inv, v.y * inv, v.z * inv, v.w * inv);
    }
}

// ---------------------------------------------------------------------------
extern "C" void kernel_launch(void* const* d_in, const int* in_sizes, int n_in,
                              void* d_out, int out_size)
{
    (void)in_sizes; (void)n_in; (void)out_size;
    const float* q   = (const float*)d_in[0];   // (T, H, 192)
    const float* kc  = (const float*)d_in[1];   // (T, 512)
    const float* kpe = (const float*)d_in[2];   // (T, 64)
    const float* wkv = (const float*)d_in[3];   // (512, 4096)
    const float* wuv = (const float*)d_in[4];   // (16, 512, 128)
    float* out = (float*)d_out;                 // (T, 2048)

    cudaFuncSetAttribute(flash_wmma, cudaFuncAttributeMaxDynamicSharedMemorySize, FLASH_SMEM);

    dim3 g1(TT / 128, 2, HH);
    kv_gemm_wmma<<<g1, 256>>>(kc, wkv, wuv);
    rope_h_kernel<<<(TT * ROPEC / 4 + 255) / 256, 256>>>(kpe);

    flash_wmma<<<(TT / 128) * HH, NTHR, FLASH_SMEM>>>(q, out);
}